// round 13
// baseline (speedup 1.0000x reference)
#include <cuda_runtime.h>

// Soft-DTW (gamma=1), 64 batches of 1024x1024, one CTA per batch.
// Warp-skewed block pipeline (KB=16), 16 warps, 2 rows/thread, log2-domain
// softmin (2 ex2 + 1 lg2 per cell), triangular block skip, sentinel-padded
// contour (no per-iter clamps), dot-form distances.
// R13: per-superstep CTA barrier replaced by PAIRWISE named barriers
// (bar.sync id=wid, 64 threads, warps w-1<->w), and the lane-0 strip reads
// are bulk-prefetched at block start (4x LDS.128 from padded rows).

#define NBATCH 64
#define NPTS   1024
#define TPB    512
#define NW     16
#define KB     16
#define NBLK   128                    // block 127 holds 15 diags (2032..2046)
#define NSUP   (NBLK + NW - 1)
#define BIGV   1.0e30f
#define SENT   1.0e17f
#define LN2F   0.69314718055994531f
#define PAD    64
#define SCPN   1160                   // indices used: [2, 1152]
#define ROWF   20                     // padded strip row (floats), 16B-aligned

__device__ float g_partial[NBATCH];

__device__ __forceinline__ float ex2f(float x) {
    float r; asm("ex2.approx.ftz.f32 %0, %1;" : "=f"(r) : "f"(x)); return r;
}
__device__ __forceinline__ float lg2f(float x) {
    float r; asm("lg2.approx.ftz.f32 %0, %1;" : "=f"(r) : "f"(x)); return r;
}
__device__ __forceinline__ void barw(int id) {
    asm volatile("bar.sync %0, 64;" :: "r"(id) : "memory");
}

// softmin in log2 domain: one exp arg is always 0 -> 2 ex2 + 1 lg2.
__device__ __forceinline__ float cellv(float a, float bq, float c, float Dl) {
    float t1  = fminf(a, bq);
    float t2  = fmaxf(a, bq);
    float mn  = fminf(t1, c);
    float mx  = fmaxf(t2, c);
    float mid = fminf(t2, fmaxf(t1, c));
    float s   = 1.0f + (ex2f(mn - mid) + ex2f(mn - mx));
    return Dl + (mn - lg2f(s));
}

typedef float BufT[2][NW][ROWF];

template<int KMAX>
__device__ __forceinline__ void run_block(
    float* __restrict__ row_out, int lane,
    const float* __restrict__ pref,
    const float4* pc, float4& cb,
    float& cur_a, float& cur_b, float& cur_a_old, float& nb2,
    float m2ax, float m2ay, float s2a,
    float m2bx, float m2by, float s2b)
{
    #pragma unroll
    for (int k = 0; k < KMAX; ++k) {
        float nb1 = __shfl_up_sync(0xFFFFFFFFu, cur_b, 1);
        if (lane == 0) nb1 = pref[k];

        float4 ca = pc[k];
        float Dla = fmaf(m2ay, ca.y, fmaf(m2ax, ca.x, s2a + ca.z));
        float Dlb = fmaf(m2by, cb.y, fmaf(m2bx, cb.x, s2b + cb.z));

        float new_a = cellv(nb2,       nb1,   cur_a, Dla);
        float new_b = cellv(cur_a_old, cur_a, cur_b, Dlb);

        if (lane == 31) row_out[k + 1] = new_b;

        nb2 = nb1; cur_a_old = cur_a; cur_a = new_a; cur_b = new_b;
        cb = ca;
    }
}

__global__ __launch_bounds__(TPB, 1)
void dtw_kernel(const float* __restrict__ snake, const float* __restrict__ contour)
{
    __shared__ float4 scp[SCPN];              // (cx, cy, cx^2+cy^2, 0)
    __shared__ __align__(16) BufT bufk;       // strip: [slot][warp][0=carry,1..16,pad]

    const int tid  = threadIdx.x;
    const int lane = tid & 31;
    const int wid  = tid >> 5;
    const int b    = blockIdx.x;
    const float SCALE = 1.2011224087864498f;  // sqrt(log2 e)

    // scp[idx] corresponds to jp = idx - PAD; valid contour at jp in [1,1024].
    for (int k = tid; k < SCPN; k += TPB) {
        int j = k - PAD;
        float cx = SENT, cy = SENT;
        if (j >= 1 && j <= NPTS) {
            float2 c = ((const float2*)contour)[b * NPTS + j - 1];
            cx = c.x * SCALE; cy = c.y * SCALE;
        }
        scp[k] = make_float4(cx, cy, fmaf(cx, cx, cy * cy), 0.f);
    }
    for (int k = tid; k < 2 * NW * ROWF; k += TPB)
        ((float*)bufk)[k] = BIGV;

    const int row_a = 2 * tid;                // rows row_a, row_a+1
    float4 s4 = ((const float4*)snake)[b * TPB + tid];
    const float sax = s4.x * SCALE, say = s4.y * SCALE;
    const float sbx = s4.z * SCALE, sby = s4.w * SCALE;
    const float m2ax = -2.f * sax, m2ay = -2.f * say;
    const float s2a  = fmaf(sax, sax, say * say);
    const float m2bx = -2.f * sbx, m2by = -2.f * sby;
    const float s2b  = fmaf(sbx, sbx, sby * sby);

    __syncthreads();                          // init fence (barrier 0, once)

    float cur_a = BIGV, cur_b = BIGV, cur_a_old = BIGV, nb2 = BIGV;
    if (tid == 0) nb2 = 0.0f;                 // R(-1,-1)=0 => cell(0,0)=D(0,0)

    const int tLo = 4 * wid;
    const int tHi = min(NBLK - 1, 4 * wid + 67);

    const int jp0 = tLo * KB - row_a + 1;
    const float4* pc = &scp[jp0 + PAD];
    float4 cb = pc[-1];

    for (int s = 0; s < NSUP; ++s) {
        // Pairwise neighbor sync (ids 1..15; increasing order => no deadlock).
        if (wid > 0)      barw(wid);
        if (wid < NW - 1) barw(wid + 1);

        const int t = s - wid;
        if (t >= tLo && t <= tHi) {
            const int slot = t & 1;
            float* row_out = &bufk[slot][wid][0];
            if (lane == 31) row_out[0] = cur_b;          // carry: diag tKB-1

            // Prefetch neighbor strip (written by warp wid-1 last superstep).
            float pref[16];
            if (lane == 0) {
                if (wid == 0) {
                    #pragma unroll
                    for (int k = 0; k < 16; ++k) pref[k] = BIGV;
                } else {
                    const float4* src = (const float4*)&bufk[slot][wid - 1][0];
                    float4 q0 = src[0], q1 = src[1], q2 = src[2], q3 = src[3];
                    pref[0]=q0.x; pref[1]=q0.y; pref[2]=q0.z; pref[3]=q0.w;
                    pref[4]=q1.x; pref[5]=q1.y; pref[6]=q1.z; pref[7]=q1.w;
                    pref[8]=q2.x; pref[9]=q2.y; pref[10]=q2.z; pref[11]=q2.w;
                    pref[12]=q3.x; pref[13]=q3.y; pref[14]=q3.z; pref[15]=q3.w;
                }
            }

            if (t < NBLK - 1) {
                run_block<16>(row_out, lane, pref, pc, cb,
                              cur_a, cur_b, cur_a_old, nb2,
                              m2ax, m2ay, s2a, m2bx, m2by, s2b);
                pc += 16;
            } else {
                run_block<15>(row_out, lane, pref, pc, cb,
                              cur_a, cur_b, cur_a_old, nb2,
                              m2ax, m2ay, s2a, m2bx, m2by, s2b);
                pc += 15;
            }
        }
    }

    if (tid == TPB - 1)
        g_partial[b] = cur_b * LN2F;          // log2 -> ln (value at diag 2046)
}

__global__ void reduce_kernel(float* __restrict__ out)
{
    float v = g_partial[threadIdx.x] + g_partial[threadIdx.x + 32];
    #pragma unroll
    for (int off = 16; off > 0; off >>= 1)
        v += __shfl_down_sync(0xFFFFFFFFu, v, off);
    if (threadIdx.x == 0)
        out[0] = v * (1.0f / NBATCH);
}

__global__ void nop_kernel() {}

extern "C" void kernel_launch(void* const* d_in, const int* in_sizes, int n_in,
                              void* d_out, int out_size)
{
    const float* snake   = (const float*)d_in[0];
    const float* contour = (const float*)d_in[1];
    float* out = (float*)d_out;

    dtw_kernel<<<NBATCH, TPB>>>(snake, contour);
    reduce_kernel<<<1, 32>>>(out);
    // Profiler alignment: makes launch #6 (ncu -s 5 -c 1) the dtw_kernel of
    // replay 2. Removed once profile data is captured.
    nop_kernel<<<1, 32>>>();
    nop_kernel<<<1, 32>>>();
    nop_kernel<<<1, 32>>>();
}